// round 5
// baseline (speedup 1.0000x reference)
#include <cuda_runtime.h>
#include <cstdint>

// sim[b,o] = sum_d |x[b,d] - c[o,d]|;  out[b,o] = beta[o] * (max(sim)*1.001 - sim[b,o])
// x[1024,512] fp32, centers[512,512] fp32, beta[512] fp32 -> out fp32 [1024,512].
// Single fused kernel, packed f32x2 math, spin grid barrier, epilogue from registers.
// R5: 512 CTAs (32x32 tiles) at 4 CTAs/SM for 2x eligible warps; KC=32 halves barriers.

#define BM 32
#define BN 32
#define KC 32          // K elements per chunk
#define KP (KC / 2)    // K float2-pairs per chunk
#define W_DIST 1.001f

__device__ int      g_max_bits = 0;   // bit pattern of global max (sims > 0 -> int order == float order)
__device__ unsigned g_count1   = 0;   // barrier arrivals
__device__ unsigned g_count2   = 0;   // post-read arrivals (guards state reset for graph replay)

__device__ __forceinline__ unsigned long long addx2(unsigned long long a, unsigned long long b) {
    unsigned long long r;
    asm("add.rn.f32x2 %0, %1, %2;" : "=l"(r) : "l"(a), "l"(b));
    return r;
}

__global__ __launch_bounds__(128, 4) void rbf_fused_kernel(
    const float* __restrict__ x,       // [B, DIN]
    const float* __restrict__ c,       // [DOUT, DIN]
    const float* __restrict__ beta,    // [DOUT]
    float* __restrict__ out,           // [B, DOUT]
    int DIN, int DOUT, unsigned NB)
{
    // double-buffered k-pair-major tiles: [buf][pair][row]
    __shared__ float2 xs[2][KP][BM];   // 8 KB
    __shared__ float2 cs[2][KP][BN];   // 8 KB (negated centers)
    __shared__ float  wmax[4];
    __shared__ float  s_gm;

    const int tid = threadIdx.x;
    const int bm = blockIdx.y;
    const int bn = blockIdx.x;
    const int tr = tid >> 4;           // 0..7   -> m = tr + 8*i  (i<4)
    const int tc = tid & 15;           // 0..15  -> n = tc + 16*j (j<2)

    unsigned long long acc[4][2];
#pragma unroll
    for (int i = 0; i < 4; i++)
#pragma unroll
        for (int j = 0; j < 2; j++) acc[i][j] = 0ULL;

    // coalesced float4 global-load mapping: 128 threads load 32 rows x 32 floats per tile
    const int rl = tid >> 2;           // 0..31 : row within tile
    const int q  = tid & 3;            // 0..3  : first float4-quad; also loads q+4
    const float4* xg = reinterpret_cast<const float4*>(x + (size_t)(bm * BM + rl) * DIN);
    const float4* cg = reinterpret_cast<const float4*>(c + (size_t)(bn * BN + rl) * DIN);

    float4 vx0 = xg[q];
    float4 vx1 = xg[q + 4];
    float4 vc0 = cg[q];
    float4 vc1 = cg[q + 4];

    // prologue: fill buffer 0
    xs[0][2 * q + 0][rl] = make_float2(vx0.x, vx0.y);
    xs[0][2 * q + 1][rl] = make_float2(vx0.z, vx0.w);
    xs[0][2 * q + 8][rl] = make_float2(vx1.x, vx1.y);
    xs[0][2 * q + 9][rl] = make_float2(vx1.z, vx1.w);
    cs[0][2 * q + 0][rl] = make_float2(-vc0.x, -vc0.y);
    cs[0][2 * q + 1][rl] = make_float2(-vc0.z, -vc0.w);
    cs[0][2 * q + 8][rl] = make_float2(-vc1.x, -vc1.y);
    cs[0][2 * q + 9][rl] = make_float2(-vc1.z, -vc1.w);
    __syncthreads();

    const int nchunks = DIN / KC;      // 16
    for (int ch = 0; ch < nchunks; ch++) {
        const int pb = ch & 1;
        // prefetch next chunk (LDG latency overlaps compute below)
        if (ch + 1 < nchunks) {
            const int base = (ch + 1) * (KC / 4);
            vx0 = xg[base + q];
            vx1 = xg[base + q + 4];
            vc0 = cg[base + q];
            vc1 = cg[base + q + 4];
        }

#pragma unroll
        for (int p = 0; p < KP; p++) {
            unsigned long long a[4], b[2];
#pragma unroll
            for (int i = 0; i < 4; i++)
                a[i] = *reinterpret_cast<const unsigned long long*>(&xs[pb][p][tr + 8 * i]);
#pragma unroll
            for (int j = 0; j < 2; j++)
                b[j] = *reinterpret_cast<const unsigned long long*>(&cs[pb][p][tc + 16 * j]);
#pragma unroll
            for (int i = 0; i < 4; i++)
#pragma unroll
                for (int j = 0; j < 2; j++) {
                    unsigned long long d = addx2(a[i], b[j]);     // x - c, packed
                    d &= 0x7FFFFFFF7FFFFFFFULL;                   // |.| both halves (alu pipe)
                    acc[i][j] = addx2(acc[i][j], d);              // packed accumulate
                }
        }

        // store prefetched chunk into the other buffer (its previous readers were
        // protected by the prior iteration's barrier)
        if (ch + 1 < nchunks) {
            const int nb = 1 - pb;
            xs[nb][2 * q + 0][rl] = make_float2(vx0.x, vx0.y);
            xs[nb][2 * q + 1][rl] = make_float2(vx0.z, vx0.w);
            xs[nb][2 * q + 8][rl] = make_float2(vx1.x, vx1.y);
            xs[nb][2 * q + 9][rl] = make_float2(vx1.z, vx1.w);
            cs[nb][2 * q + 0][rl] = make_float2(-vc0.x, -vc0.y);
            cs[nb][2 * q + 1][rl] = make_float2(-vc0.z, -vc0.w);
            cs[nb][2 * q + 8][rl] = make_float2(-vc1.x, -vc1.y);
            cs[nb][2 * q + 9][rl] = make_float2(-vc1.z, -vc1.w);
        }
        __syncthreads();
    }

    // ---- per-thread sim fragment + block max ----
    float s[4][2];
    float tmax = 0.0f;
#pragma unroll
    for (int i = 0; i < 4; i++)
#pragma unroll
        for (int j = 0; j < 2; j++) {
            float2 v = *reinterpret_cast<float2*>(&acc[i][j]);
            s[i][j] = v.x + v.y;
            tmax = fmaxf(tmax, s[i][j]);
        }
#pragma unroll
    for (int off = 16; off > 0; off >>= 1)
        tmax = fmaxf(tmax, __shfl_xor_sync(0xffffffffu, tmax, off));
    if ((tid & 31) == 0) wmax[tid >> 5] = tmax;
    __syncthreads();

    // ---- grid barrier (all 512 CTAs co-resident: launch_bounds(128,4), 512 <= 4*148) ----
    if (tid == 0) {
        float bmx = fmaxf(fmaxf(wmax[0], wmax[1]), fmaxf(wmax[2], wmax[3]));
        atomicMax(&g_max_bits, __float_as_int(bmx));
        __threadfence();                       // max visible before arrival
        atomicAdd(&g_count1, 1u);
        while (*((volatile unsigned*)&g_count1) < NB) { __nanosleep(64); }
        __threadfence();                       // acquire
        s_gm = __int_as_float(*((volatile int*)&g_max_bits)) * W_DIST;
        // signal "max consumed"; last arriver resets state for the next graph replay
        unsigned old = atomicAdd(&g_count2, 1u);
        if (old == NB - 1u) {
            g_max_bits = 0;
            g_count1   = 0;
            g_count2   = 0;
        }
    }
    __syncthreads();
    const float gm = s_gm;

    // ---- epilogue from registers ----
    float bet[2];
#pragma unroll
    for (int j = 0; j < 2; j++) bet[j] = beta[bn * BN + tc + 16 * j];

#pragma unroll
    for (int i = 0; i < 4; i++) {
        const int row = bm * BM + tr + 8 * i;
        float* orow = out + (size_t)row * DOUT + bn * BN;
#pragma unroll
        for (int j = 0; j < 2; j++)
            orow[tc + 16 * j] = bet[j] * (gm - s[i][j]);
    }
}

extern "C" void kernel_launch(void* const* d_in, const int* in_sizes, int n_in,
                              void* d_out, int out_size)
{
    const float* x    = (const float*)d_in[0];
    const float* c    = (const float*)d_in[1];
    const float* beta = (const float*)d_in[2];
    float* out = (float*)d_out;

    const int DOUT = in_sizes[2];
    const int DIN  = in_sizes[1] / DOUT;
    const int B    = in_sizes[0] / DIN;

    dim3 grid(DOUT / BN, B / BM);
    const unsigned NB = grid.x * grid.y;
    rbf_fused_kernel<<<grid, 128>>>(x, c, beta, out, DIN, DOUT, NB);
}